// round 5
// baseline (speedup 1.0000x reference)
#include <cuda_runtime.h>
#include <cuda_fp16.h>
#include <cstdint>

#define B_SZ   1024
#define IN_SZ  128
#define OUT_SZ 10000
#define KCEN   16
#define NT     79              // 79 n-tiles of 128 = 10112 >= 10000
#define MT     8               // 8 m-tiles of 128
#define SSC    64.0f
#define LDA    136             // smem pitch in halves (272B) -> conflict-free ldmatrix
#define LDB    136
#define ATILE  (128*LDA)       // halves
#define BTILE  (128*LDB)
#define SMEM_BYTES ((ATILE + 2*BTILE)*2)   // 104448

// ---------------- device scratch ----------------
__device__ uint4  g_wimg[(size_t)NT*KCEN*2048];     // 41.4 MB fp16 tiles [k][n], 32KB each
__device__ uint4  g_ximg[MT*2048];                  // 256 KB fp16 tiles [m][k]
__device__ float  g_xnf[B_SZ*IN_SZ];                // exact normalized x (fp32)
__device__ float  g_clab[B_SZ*KCEN];                // exact label-column cos per kc
__device__ float2 g_part[(size_t)B_SZ*NT];          // per (row, n-tile) (max, sumexp) non-label
__device__ float  g_cosfa[B_SZ], g_sinfa[B_SZ], g_costhr[B_SZ];
__device__ float  g_loss[B_SZ], g_corr[B_SZ];

// ---------------- helpers ----------------
__device__ __forceinline__ uint32_t smem_u32(const void* p) {
    uint32_t a;
    asm("{ .reg .u64 t; cvta.to.shared.u64 t, %1; cvt.u32.u64 %0, t; }" : "=r"(a) : "l"(p));
    return a;
}
__device__ __forceinline__ void cp_async16(uint32_t saddr, const void* gptr) {
    asm volatile("cp.async.cg.shared.global [%0], [%1], 16;\n" :: "r"(saddr), "l"(gptr));
}
#define CP_COMMIT() asm volatile("cp.async.commit_group;\n")

#define LDSM_X4(r0,r1,r2,r3,addr) \
    asm volatile("ldmatrix.sync.aligned.m8n8.x4.shared.b16 {%0,%1,%2,%3}, [%4];" \
        : "=r"(r0),"=r"(r1),"=r"(r2),"=r"(r3) : "r"(addr))
#define LDSM_X4_T(r0,r1,r2,r3,addr) \
    asm volatile("ldmatrix.sync.aligned.m8n8.x4.trans.shared.b16 {%0,%1,%2,%3}, [%4];" \
        : "=r"(r0),"=r"(r1),"=r"(r2),"=r"(r3) : "r"(addr))
#define MMA16816(c0,c1,c2,c3,a0,a1,a2,a3,b0,b1) \
    asm volatile("mma.sync.aligned.m16n8k16.row.col.f32.f16.f16.f32 " \
        "{%0,%1,%2,%3},{%4,%5,%6,%7},{%8,%9},{%0,%1,%2,%3};" \
        : "+f"(c0),"+f"(c1),"+f"(c2),"+f"(c3) \
        : "r"(a0),"r"(a1),"r"(a2),"r"(a3),"r"(b0),"r"(b1))

// ---------------- prep_x: normalize rows -> fp16 [m][k] + exact xn + consts
__global__ void prep_x_kernel(const float* __restrict__ x,
                              const float* __restrict__ factor) {
    int b = blockIdx.x, f = threadIdx.x;        // 128 threads
    float v = x[b*IN_SZ + f];
    float s = v*v;
    #pragma unroll
    for (int o = 16; o; o >>= 1) s += __shfl_xor_sync(0xffffffffu, s, o);
    __shared__ float ws[4];
    if ((f & 31) == 0) ws[f >> 5] = s;
    __syncthreads();
    float tot = ws[0] + ws[1] + ws[2] + ws[3];
    float rinv = 1.f / fmaxf(sqrtf(tot), 1e-12f);
    float xn = v * rinv;
    ((__half*)g_ximg)[(b >> 7)*16384 + (b & 127)*128 + f] = __float2half(xn);
    g_xnf[b*IN_SZ + f] = xn;
    if (f == 0) {
        float fa = powf(1.5f, factor[b] * (1.f/12.f)) * 0.5f;
        float cfa = cosf(fa);
        g_cosfa[b] = cfa; g_sinfa[b] = sinf(fa); g_costhr[b] = -cfa;
    }
}

// ---------------- prep_w: one-pass normalize -> fp16 [k][n] tiles + exact label dots
__global__ void prep_w_kernel(const float* __restrict__ w,
                              const int* __restrict__ label) {
    extern __shared__ float tile[];             // 128 x 129 fp32: tile[f][n]
    __shared__ float sums[256];
    __shared__ float rn[128];
    int kc = blockIdx.x, nt = blockIdx.y, t = threadIdx.x;   // 256 threads
    const float* wk = w + (size_t)kc * IN_SZ * OUT_SZ;
    int o0 = nt * 128;

    #pragma unroll 4
    for (int i = 0; i < 64; i++) {
        int idx = i*256 + t;
        int f = idx >> 7, ol = idx & 127, o = o0 + ol;
        tile[f*129 + ol] = (o < OUT_SZ) ? wk[(size_t)f*OUT_SZ + o] : 0.f;
    }
    __syncthreads();
    {
        int ol = t & 127, half = t >> 7;
        float ss = 0.f;
        #pragma unroll 8
        for (int f = half*64; f < half*64 + 64; f++) { float v = tile[f*129 + ol]; ss += v*v; }
        sums[t] = ss;
    }
    __syncthreads();
    if (t < 128)
        rn[t] = 1.f / fmaxf(sqrtf(sums[t] + sums[t+128]), 1e-12f);
    __syncthreads();

    // exact label-column cos (rare matches; ~13 per block)
    for (int j = t; j < B_SZ; j += 256) {
        int ll = label[j] - o0;
        if (ll >= 0 && ll < 128) {
            const float* xr = g_xnf + j*IN_SZ;
            float d = 0.f;
            #pragma unroll 8
            for (int f = 0; f < IN_SZ; f++) d += xr[f] * tile[f*129 + ll];
            g_clab[j*KCEN + kc] = d * rn[ll];
        }
    }

    // fp16 [k][n] tile write: row f (k), 128 n contiguous (256B per row)
    char* img = (char*)g_wimg + ((size_t)nt*KCEN + kc)*32768;
    #pragma unroll
    for (int i = 0; i < 8; i++) {
        int ci = i*256 + t;
        int f = ci >> 4, chunk = ci & 15;
        __align__(16) __half hs[8];
        #pragma unroll
        for (int j = 0; j < 8; j++) {
            int n = chunk*8 + j;
            hs[j] = __float2half(tile[f*129 + n] * rn[n]);
        }
        *(uint4*)(img + f*256 + chunk*16) = *(const uint4*)hs;
    }
}

// ---------------- fused fp16 GEMM (round-1 mainloop) + online softmax partials
__global__ void __launch_bounds__(256, 1) gemm_kernel(const int* __restrict__ label) {
    extern __shared__ __half sm[];
    __shared__ float sm_m[128], sm_s[128];
    __half* As = sm;
    __half* Bs = sm + ATILE;

    int tid = threadIdx.x, w = tid >> 5, lane = tid & 31;
    int mtile = blockIdx.x, nt = blockIdx.y;
    int wm = w & 3, wn = w >> 2;

    const char* ximg = (const char*)g_ximg + mtile*32768;
    const char* wimg = (const char*)g_wimg + (size_t)nt*KCEN*32768;

    // prologue: A + B0 (A rows: m, pitch 272B smem; gmem row 256B)
    #pragma unroll
    for (int i = 0; i < 8; i++) {
        int ci = i*256 + tid;
        cp_async16((uint32_t)__cvta_generic_to_shared(As + (ci >> 4)*LDA + (ci & 15)*8),
                   ximg + ci*16);
    }
    #pragma unroll
    for (int i = 0; i < 8; i++) {
        int ci = i*256 + tid;
        cp_async16((uint32_t)__cvta_generic_to_shared(Bs + (ci >> 4)*LDB + (ci & 15)*8),
                   wimg + ci*16);
    }
    CP_COMMIT();

    uint32_t sm32 = smem_u32(sm);
    uint32_t aA = sm32 + ((wm*32 + (lane & 15))*LDA + (lane >> 4)*8)*2;
    uint32_t aB = sm32 + ATILE*2 + ((lane & 15)*LDB + wn*64 + (lane >> 4)*8)*2;

    float mx[2][8][4];
    #pragma unroll
    for (int i = 0; i < 2; i++)
        #pragma unroll
        for (int j = 0; j < 8; j++)
            #pragma unroll
            for (int c = 0; c < 4; c++) mx[i][j][c] = -3.0e38f;

    for (int kc = 0; kc < KCEN; kc++) {
        int buf = kc & 1;
        if (kc < KCEN-1) {
            const char* src = wimg + (size_t)(kc + 1)*32768;
            __half* dst = Bs + (buf ^ 1)*BTILE;
            #pragma unroll
            for (int i = 0; i < 8; i++) {
                int ci = i*256 + tid;
                cp_async16((uint32_t)__cvta_generic_to_shared(dst + (ci >> 4)*LDB + (ci & 15)*8),
                           src + ci*16);
            }
        }
        CP_COMMIT();
        asm volatile("cp.async.wait_group 1;");
        __syncthreads();

        float acc[2][8][4];
        #pragma unroll
        for (int i = 0; i < 2; i++)
            #pragma unroll
            for (int j = 0; j < 8; j++)
                #pragma unroll
                for (int c = 0; c < 4; c++) acc[i][j][c] = 0.f;

        #pragma unroll
        for (int ks = 0; ks < 8; ks++) {
            uint32_t a[2][4];
            #pragma unroll
            for (int mt = 0; mt < 2; mt++)
                LDSM_X4(a[mt][0], a[mt][1], a[mt][2], a[mt][3],
                        aA + mt*16*LDA*2 + ks*32);
            uint32_t bq[8][2];
            #pragma unroll
            for (int p = 0; p < 4; p++)
                LDSM_X4_T(bq[2*p][0], bq[2*p][1], bq[2*p+1][0], bq[2*p+1][1],
                          aB + buf*BTILE*2 + ks*16*LDB*2 + p*32);
            #pragma unroll
            for (int mt = 0; mt < 2; mt++)
                #pragma unroll
                for (int nf = 0; nf < 8; nf++)
                    MMA16816(acc[mt][nf][0], acc[mt][nf][1], acc[mt][nf][2], acc[mt][nf][3],
                             a[mt][0], a[mt][1], a[mt][2], a[mt][3],
                             bq[nf][0], bq[nf][1]);
        }
        #pragma unroll
        for (int i = 0; i < 2; i++)
            #pragma unroll
            for (int j = 0; j < 8; j++)
                #pragma unroll
                for (int c = 0; c < 4; c++)
                    mx[i][j][c] = fmaxf(mx[i][j][c], acc[i][j][c]);
        __syncthreads();
    }

    // ---- fused epilogue: 4 row-states per thread, 16 cols each ----
    int rbase = mtile*128 + wm*32 + (lane >> 2);
    int labv[4];
    #pragma unroll
    for (int st = 0; st < 4; st++)
        labv[st] = label[rbase + (st >> 1)*16 + (st & 1)*8];

    float m4[4] = {-3.0e38f, -3.0e38f, -3.0e38f, -3.0e38f};
    float s4[4] = {0.f, 0.f, 0.f, 0.f};
    int colb = nt*128 + wn*64;

    #pragma unroll
    for (int nf = 0; nf < 8; nf++)
        #pragma unroll
        for (int c = 0; c < 4; c++) {
            int col = colb + nf*8 + (lane & 3)*2 + (c & 1);
            #pragma unroll
            for (int mt = 0; mt < 2; mt++) {
                int st = mt*2 + (c >> 1);
                if (col < OUT_SZ && col != labv[st]) {
                    float cv = mx[mt][nf][c];
                    cv = fminf(fmaxf(cv, -1.0f + 1e-6f), 1.0f - 1e-6f);
                    float l = cv * SSC;
                    if (l > m4[st]) { s4[st] = s4[st]*__expf(m4[st] - l) + 1.f; m4[st] = l; }
                    else            { s4[st] += __expf(l - m4[st]); }
                }
            }
        }

    // merge the 4 lanes of each row-quad
    #pragma unroll
    for (int o = 1; o <= 2; o <<= 1) {
        #pragma unroll
        for (int st = 0; st < 4; st++) {
            float mo = __shfl_xor_sync(0xffffffffu, m4[st], o);
            float so = __shfl_xor_sync(0xffffffffu, s4[st], o);
            float M = fmaxf(m4[st], mo);
            s4[st] = s4[st]*__expf(m4[st] - M) + so*__expf(mo - M);
            m4[st] = M;
        }
    }
    // merge the two column-half warps
    if (wn == 0 && (lane & 3) == 0) {
        #pragma unroll
        for (int st = 0; st < 4; st++) {
            int rl = wm*32 + (lane >> 2) + (st >> 1)*16 + (st & 1)*8;
            sm_m[rl] = m4[st]; sm_s[rl] = s4[st];
        }
    }
    __syncthreads();
    if (wn == 1 && (lane & 3) == 0) {
        #pragma unroll
        for (int st = 0; st < 4; st++) {
            int rl = wm*32 + (lane >> 2) + (st >> 1)*16 + (st & 1)*8;
            float mo = sm_m[rl], so = sm_s[rl];
            float M = fmaxf(m4[st], mo);
            float S = s4[st]*__expf(m4[st] - M) + so*__expf(mo - M);
            g_part[(size_t)(mtile*128 + rl)*NT + nt] = make_float2(M, S);
        }
    }
}

// ---------------- combine n-tile partials + exact label logit per row -------
__global__ void rowcombine_kernel(const int* __restrict__ label) {
    int r = blockIdx.x, t = threadIdx.x;        // 128 threads
    float m = -3.0e38f, s = 0.f;
    if (t < NT) { float2 p = g_part[(size_t)r*NT + t]; m = p.x; s = p.y; }
    __shared__ float rm[128], rs[128];
    rm[t] = m; rs[t] = s;
    __syncthreads();
    for (int st = 64; st; st >>= 1) {
        if (t < st) {
            float m1 = rm[t], m2 = rm[t+st];
            float M = fmaxf(m1, m2);
            rs[t] = rs[t]*__expf(m1 - M) + rs[t+st]*__expf(m2 - M);
            rm[t] = M;
        }
        __syncthreads();
    }
    if (t == 0) {
        float c = -2.f;
        #pragma unroll
        for (int k = 0; k < KCEN; k++) c = fmaxf(c, g_clab[r*KCEN + k]);
        c = fminf(fmaxf(c, -1.0f + 1e-6f), 1.0f - 1e-6f);
        float l;
        if (c >= g_costhr[r])
            l = (c * g_cosfa[r] - sqrtf(fmaxf(1.f - c*c, 0.f)) * g_sinfa[r]) * SSC;
        else
            l = c * SSC;
        float Mn = rm[0], Sn = rs[0];
        float M = fmaxf(Mn, l);
        float S = Sn*__expf(Mn - M) + __expf(l - M);
        g_loss[r] = logf(S) + M - l;
        g_corr[r] = (l > Mn) ? 1.f : 0.f;
        (void)label;
    }
}

// ---------------- final reduction ---------------------------------------------
__global__ void fin_kernel(float* __restrict__ out) {
    int t = threadIdx.x;                        // 1024 threads
    __shared__ float sl[1024], sc[1024];
    sl[t] = g_loss[t]; sc[t] = g_corr[t];
    __syncthreads();
    for (int st = 512; st; st >>= 1) {
        if (t < st) { sl[t] += sl[t+st]; sc[t] += sc[t+st]; }
        __syncthreads();
    }
    if (t == 0) {
        out[0] = sl[0] * (1.f/1024.f);
        out[1] = sc[0] * (100.f/1024.f);
    }
}

// ---------------- launch --------------------------------------------------------
extern "C" void kernel_launch(void* const* d_in, const int* in_sizes, int n_in,
                              void* d_out, int out_size) {
    const float* x      = (const float*)d_in[0];
    const float* factor = (const float*)d_in[1];
    const int*   label  = (const int*)  d_in[2];
    const float* w      = (const float*)d_in[3];
    float* out = (float*)d_out;

    cudaFuncSetAttribute(prep_w_kernel, cudaFuncAttributeMaxDynamicSharedMemorySize, 128*129*4);
    cudaFuncSetAttribute(gemm_kernel,   cudaFuncAttributeMaxDynamicSharedMemorySize, SMEM_BYTES);

    prep_x_kernel<<<B_SZ, 128>>>(x, factor);
    prep_w_kernel<<<dim3(KCEN, NT), 256, 128*129*4>>>(w, label);
    gemm_kernel<<<dim3(MT, NT), 256, SMEM_BYTES>>>(label);
    rowcombine_kernel<<<B_SZ, 128>>>(label);
    fin_kernel<<<1, 1024>>>(out);
}

// round 6
// speedup vs baseline: 1.2019x; 1.2019x over previous
#include <cuda_runtime.h>
#include <cuda_fp16.h>
#include <cstdint>

#define B_SZ   1024
#define IN_SZ  128
#define OUT_SZ 10000
#define OUTP   10112            // 79 * 128, padded
#define KCEN   16
#define NT     79
#define SSC    64.0f

#define LDA 136                 // 128 + 8 halves pad -> conflict-free ldmatrix
#define LDB 136
#define ATILE (128*LDA)
#define BTILE (128*LDB)
#define SMEM_HALVES (ATILE + 2*BTILE)
#define SMEM_BYTES  (SMEM_HALVES*2)

// ---------------- device scratch ----------------
__device__ float4 g_xh4[(B_SZ*IN_SZ)/8];                       // 256 KB fp16
__device__ float4 g_wh4[((size_t)KCEN*IN_SZ*OUTP)/8];          // 41.4 MB fp16 (normalized)
__device__ float  g_cos[(size_t)B_SZ*OUTP];                    // 41.4 MB fp32
__device__ float  g_cosfa[B_SZ], g_sinfa[B_SZ], g_costhr[B_SZ];
__device__ float  g_loss[B_SZ], g_corr[B_SZ];

// ---------------- prep_x (round-1 verbatim) --------------------------------
__global__ void prep_x_kernel(const float* __restrict__ x,
                              const float* __restrict__ factor) {
    int b = blockIdx.x, f = threadIdx.x;     // 128 threads
    float v = x[b*IN_SZ + f];
    float s = v*v;
    #pragma unroll
    for (int o = 16; o; o >>= 1) s += __shfl_xor_sync(0xffffffffu, s, o);
    __shared__ float ws[4];
    if ((f & 31) == 0) ws[f >> 5] = s;
    __syncthreads();
    float tot = ws[0] + ws[1] + ws[2] + ws[3];
    float rinv = 1.f / fmaxf(sqrtf(tot), 1e-12f);
    ((__half*)g_xh4)[b*IN_SZ + f] = __float2half(v * rinv);
    if (f == 0) {
        float fa = powf(1.5f, factor[b] * (1.f/12.f)) * 0.5f;
        float cfa = cosf(fa);
        g_cosfa[b] = cfa;
        g_sinfa[b] = sinf(fa);
        g_costhr[b] = -cfa;                  // cos(pi - fa)
    }
}

// ---------------- prep_w: one-pass smem-tile normalize -> g_wh4 [k][f][o] ---
__global__ void prep_w_kernel(const float* __restrict__ w) {
    extern __shared__ float tile[];             // 128 x 129 fp32: tile[f][ol]
    __shared__ float sums[256];
    __shared__ float rn[128];
    int kc = blockIdx.x, nt = blockIdx.y, t = threadIdx.x;   // 256 threads
    const float* wk = w + (size_t)kc * IN_SZ * OUT_SZ;
    int o0 = nt * 128;

    #pragma unroll 4
    for (int i = 0; i < 64; i++) {
        int idx = i*256 + t;
        int f = idx >> 7, ol = idx & 127, o = o0 + ol;
        tile[f*129 + ol] = (o < OUT_SZ) ? wk[(size_t)f*OUT_SZ + o] : 0.f;
    }
    __syncthreads();
    {
        int ol = t & 127, half = t >> 7;
        float ss = 0.f;
        #pragma unroll 8
        for (int f = half*64; f < half*64 + 64; f++) { float v = tile[f*129 + ol]; ss += v*v; }
        sums[t] = ss;
    }
    __syncthreads();
    if (t < 128)
        rn[t] = 1.f / fmaxf(sqrtf(sums[t] + sums[t+128]), 1e-12f);
    __syncthreads();

    // write fp16 into [k][f][o] (OUTP-wide rows), coalesced 16B chunks
    __half* wh = (__half*)g_wh4;
    size_t base = (size_t)kc*IN_SZ*OUTP + o0;
    #pragma unroll
    for (int i = 0; i < 8; i++) {
        int ci = i*256 + t;
        int f = ci >> 4, chunk = ci & 15;
        __align__(16) __half hs[8];
        #pragma unroll
        for (int j = 0; j < 8; j++) {
            int n = chunk*8 + j;
            hs[j] = __float2half(tile[f*129 + n] * rn[n]);
        }
        *(uint4*)(wh + base + (size_t)f*OUTP + chunk*8) = *(const uint4*)hs;
    }
}

// ---------------- GEMM helpers (round-1 verbatim) ---------------------------
__device__ __forceinline__ void cp_async16(uint32_t saddr, const void* gptr) {
    asm volatile("cp.async.cg.shared.global [%0], [%1], 16;\n" :: "r"(saddr), "l"(gptr));
}
#define CP_COMMIT() asm volatile("cp.async.commit_group;\n")
#define CP_WAIT1()  asm volatile("cp.async.wait_group 1;\n")

#define LDSM_X4(r0,r1,r2,r3,addr) \
    asm volatile("ldmatrix.sync.aligned.m8n8.x4.shared.b16 {%0,%1,%2,%3}, [%4];" \
        : "=r"(r0),"=r"(r1),"=r"(r2),"=r"(r3) : "r"(addr))
#define LDSM_X4_T(r0,r1,r2,r3,addr) \
    asm volatile("ldmatrix.sync.aligned.m8n8.x4.trans.shared.b16 {%0,%1,%2,%3}, [%4];" \
        : "=r"(r0),"=r"(r1),"=r"(r2),"=r"(r3) : "r"(addr))
#define MMA16816(c0,c1,c2,c3,a0,a1,a2,a3,b0,b1) \
    asm volatile("mma.sync.aligned.m16n8k16.row.col.f32.f16.f16.f32 " \
        "{%0,%1,%2,%3},{%4,%5,%6,%7},{%8,%9},{%0,%1,%2,%3};" \
        : "+f"(c0),"+f"(c1),"+f"(c2),"+f"(c3) \
        : "r"(a0),"r"(a1),"r"(a2),"r"(a3),"r"(b0),"r"(b1))

__device__ __forceinline__ void load_b_tile(__half* Bs, const __half* wh,
                                            int tid, int n0, int kc, int buf) {
    int chunk = tid & 15, r0 = tid >> 4;
    const __half* src = wh + (size_t)kc*IN_SZ*OUTP + n0;
    __half* dst = Bs + buf*BTILE;
    #pragma unroll
    for (int it = 0; it < 8; it++) {
        int row = it*16 + r0;
        cp_async16((uint32_t)__cvta_generic_to_shared(dst + row*LDB + chunk*8),
                   src + (size_t)row*OUTP + chunk*8);
    }
}

// ---------------- main GEMM (round-1 verbatim) ------------------------------
__global__ void __launch_bounds__(256, 1) gemm_kernel() {
    extern __shared__ __half sm[];
    __half* As = sm;
    __half* Bs = sm + ATILE;
    const __half* xh = (const __half*)g_xh4;
    const __half* wh = (const __half*)g_wh4;

    int tid = threadIdx.x;
    int n0 = blockIdx.x * 128;
    int m0 = blockIdx.y * 128;

    {
        int chunk = tid & 15, r0 = tid >> 4;
        #pragma unroll
        for (int it = 0; it < 8; it++) {
            int row = it*16 + r0;
            cp_async16((uint32_t)__cvta_generic_to_shared(As + row*LDA + chunk*8),
                       xh + (size_t)(m0 + row)*IN_SZ + chunk*8);
        }
    }
    load_b_tile(Bs, wh, tid, n0, 0, 0);
    CP_COMMIT();

    int wid = tid >> 5, lane = tid & 31;
    int wm = wid & 3, wn = wid >> 2;

    uint32_t smem_u32v = (uint32_t)__cvta_generic_to_shared(sm);
    uint32_t aA = smem_u32v + ((wm*32 + (lane & 15))*LDA + (lane >> 4)*8)*2;
    uint32_t aB = smem_u32v + ATILE*2 + ((lane & 15)*LDB + wn*64 + (lane >> 4)*8)*2;

    float mx[2][8][4];
    #pragma unroll
    for (int i = 0; i < 2; i++)
        #pragma unroll
        for (int j = 0; j < 8; j++)
            #pragma unroll
            for (int c = 0; c < 4; c++) mx[i][j][c] = -3.4e38f;

    for (int kc = 0; kc < KCEN; kc++) {
        int buf = kc & 1;
        if (kc < KCEN-1) load_b_tile(Bs, wh, tid, n0, kc+1, buf ^ 1);
        CP_COMMIT();
        CP_WAIT1();
        __syncthreads();

        float acc[2][8][4];
        #pragma unroll
        for (int i = 0; i < 2; i++)
            #pragma unroll
            for (int j = 0; j < 8; j++)
                #pragma unroll
                for (int c = 0; c < 4; c++) acc[i][j][c] = 0.f;

        #pragma unroll
        for (int ks = 0; ks < 8; ks++) {
            uint32_t a[2][4];
            #pragma unroll
            for (int mt = 0; mt < 2; mt++)
                LDSM_X4(a[mt][0], a[mt][1], a[mt][2], a[mt][3],
                        aA + mt*16*LDA*2 + ks*32);
            uint32_t bq[8][2];
            #pragma unroll
            for (int p = 0; p < 4; p++)
                LDSM_X4_T(bq[2*p][0], bq[2*p][1], bq[2*p+1][0], bq[2*p+1][1],
                          aB + buf*BTILE*2 + ks*16*LDB*2 + p*32);
            #pragma unroll
            for (int mt = 0; mt < 2; mt++)
                #pragma unroll
                for (int nt = 0; nt < 8; nt++)
                    MMA16816(acc[mt][nt][0], acc[mt][nt][1], acc[mt][nt][2], acc[mt][nt][3],
                             a[mt][0], a[mt][1], a[mt][2], a[mt][3],
                             bq[nt][0], bq[nt][1]);
        }
        #pragma unroll
        for (int i = 0; i < 2; i++)
            #pragma unroll
            for (int j = 0; j < 8; j++)
                #pragma unroll
                for (int c = 0; c < 4; c++)
                    mx[i][j][c] = fmaxf(mx[i][j][c], acc[i][j][c]);
        __syncthreads();
    }

    int rbase = m0 + wm*32 + (lane >> 2);
    int cbase = n0 + wn*64 + (lane & 3)*2;
    #pragma unroll
    for (int mt = 0; mt < 2; mt++)
        #pragma unroll
        for (int nt = 0; nt < 8; nt++) {
            int r = rbase + mt*16, c = cbase + nt*8;
            *(float2*)&g_cos[(size_t)r*OUTP + c]      = make_float2(mx[mt][nt][0], mx[mt][nt][1]);
            *(float2*)&g_cos[(size_t)(r+8)*OUTP + c]  = make_float2(mx[mt][nt][2], mx[mt][nt][3]);
        }
}

// ---------------- epilogue v2: batched loads, 2-phase softmax ----------------
__global__ void __launch_bounds__(256) epi_kernel(const int* __restrict__ label) {
    int r = blockIdx.x, t = threadIdx.x;     // 256 threads, 40 cols each
    const float* row = g_cos + (size_t)r*OUTP;
    int lab = label[r];
    float cfa = g_cosfa[r], sfa = g_sinfa[r], cthr = g_costhr[r];

    __shared__ float s_mn[8], s_sum[8];
    __shared__ float s_lab;

    // phase 0: batched loads (high MLP)
    float v[40];
    #pragma unroll
    for (int j = 0; j < 40; j++) {
        int o = j*256 + t;
        v[j] = (o < OUT_SZ) ? row[o] : 1.0f;   // pad maps to l=64, overwritten below
    }

    // phase 1: logits + local max (label handled exactly)
    const float CLO = -1.0f + 1e-6f, CHI = 1.0f - 1e-6f;
    float mnon = -3.0e38f;
    #pragma unroll
    for (int j = 0; j < 40; j++) {
        int o = j*256 + t;
        float c = fminf(fmaxf(v[j], CLO), CHI);
        float l = c * SSC;
        if (o == lab) {
            if (c >= cthr)
                l = (c*cfa - sqrtf(fmaxf(1.f - c*c, 0.f))*sfa) * SSC;
            s_lab = l;
            v[j] = l;
        } else if (o < OUT_SZ) {
            v[j] = l;
            mnon = fmaxf(mnon, l);
        } else {
            v[j] = -3.0e38f;
        }
    }
    // block max (non-label)
    #pragma unroll
    for (int o = 16; o; o >>= 1) mnon = fmaxf(mnon, __shfl_xor_sync(0xffffffffu, mnon, o));
    if ((t & 31) == 0) s_mn[t >> 5] = mnon;
    __syncthreads();
    float Mn = fmaxf(fmaxf(fmaxf(s_mn[0], s_mn[1]), fmaxf(s_mn[2], s_mn[3])),
                     fmaxf(fmaxf(s_mn[4], s_mn[5]), fmaxf(s_mn[6], s_mn[7])));
    float llab = s_lab;
    float M = fmaxf(Mn, llab);

    // phase 2: independent expf sum
    float s = 0.f;
    #pragma unroll
    for (int j = 0; j < 40; j++) s += __expf(v[j] - M);
    #pragma unroll
    for (int o = 16; o; o >>= 1) s += __shfl_xor_sync(0xffffffffu, s, o);
    if ((t & 31) == 0) s_sum[t >> 5] = s;
    __syncthreads();
    if (t == 0) {
        float S = s_sum[0]+s_sum[1]+s_sum[2]+s_sum[3]
                + s_sum[4]+s_sum[5]+s_sum[6]+s_sum[7];
        g_loss[r] = logf(S) + M - llab;
        g_corr[r] = (llab > Mn) ? 1.f : 0.f;
    }
}

// ---------------- final reduction ------------------------------------------
__global__ void fin_kernel(float* __restrict__ out) {
    int t = threadIdx.x;                     // 1024 threads
    __shared__ float sl[1024], sc[1024];
    sl[t] = g_loss[t]; sc[t] = g_corr[t];
    __syncthreads();
    for (int st = 512; st > 0; st >>= 1) {
        if (t < st) { sl[t] += sl[t+st]; sc[t] += sc[t+st]; }
        __syncthreads();
    }
    if (t == 0) {
        out[0] = sl[0] * (1.f/1024.f);
        out[1] = sc[0] * (100.f/1024.f);
    }
}

// ---------------- launch ----------------------------------------------------
extern "C" void kernel_launch(void* const* d_in, const int* in_sizes, int n_in,
                              void* d_out, int out_size) {
    const float* x      = (const float*)d_in[0];
    const float* factor = (const float*)d_in[1];
    const int*   label  = (const int*)  d_in[2];
    const float* w      = (const float*)d_in[3];
    float* out = (float*)d_out;

    cudaFuncSetAttribute(prep_w_kernel, cudaFuncAttributeMaxDynamicSharedMemorySize, 128*129*4);
    cudaFuncSetAttribute(gemm_kernel,   cudaFuncAttributeMaxDynamicSharedMemorySize, SMEM_BYTES);

    prep_x_kernel<<<B_SZ, 128>>>(x, factor);
    prep_w_kernel<<<dim3(KCEN, NT), 256, 128*129*4>>>(w);
    gemm_kernel<<<dim3(NT, B_SZ/128), 256, SMEM_BYTES>>>();
    epi_kernel<<<B_SZ, 256>>>(label);
    fin_kernel<<<1, 1024>>>(out);
}

// round 7
// speedup vs baseline: 1.2453x; 1.0361x over previous
#include <cuda_runtime.h>
#include <cuda_fp16.h>
#include <cstdint>

#define B_SZ   1024
#define IN_SZ  128
#define OUT_SZ 10000
#define OUTP   10112            // 79 * 128, padded
#define KCEN   16
#define NT     79
#define NT1    16               // n-tiles in first GEMM chunk
#define SSC    64.0f

#define LDA 136                 // 128 + 8 halves pad -> conflict-free ldmatrix
#define LDB 136
#define ATILE (128*LDA)
#define BTILE (128*LDB)
#define SMEM_HALVES (ATILE + 2*BTILE)
#define SMEM_BYTES  (SMEM_HALVES*2)

// ---------------- device scratch ----------------
__device__ float4  g_xh4[(B_SZ*IN_SZ)/8];                      // 256 KB fp16
__device__ float4  g_wh4[((size_t)KCEN*IN_SZ*OUTP)/8];         // 41.4 MB fp16 (normalized)
__device__ __half2 g_cosh[((size_t)B_SZ*OUTP)/2 + 256];        // 20.7 MB fp16 cos (+pad)
__device__ float   g_cosfa[B_SZ], g_sinfa[B_SZ], g_costhr[B_SZ];
__device__ float   g_loss[B_SZ], g_corr[B_SZ];

// ---------------- prep_x (round-1 verbatim) --------------------------------
__global__ void prep_x_kernel(const float* __restrict__ x,
                              const float* __restrict__ factor) {
    int b = blockIdx.x, f = threadIdx.x;     // 128 threads
    float v = x[b*IN_SZ + f];
    float s = v*v;
    #pragma unroll
    for (int o = 16; o; o >>= 1) s += __shfl_xor_sync(0xffffffffu, s, o);
    __shared__ float ws[4];
    if ((f & 31) == 0) ws[f >> 5] = s;
    __syncthreads();
    float tot = ws[0] + ws[1] + ws[2] + ws[3];
    float rinv = 1.f / fmaxf(sqrtf(tot), 1e-12f);
    ((__half*)g_xh4)[b*IN_SZ + f] = __float2half(v * rinv);
    if (f == 0) {
        float fa = powf(1.5f, factor[b] * (1.f/12.f)) * 0.5f;
        float cfa = cosf(fa);
        g_cosfa[b] = cfa;
        g_sinfa[b] = sinf(fa);
        g_costhr[b] = -cfa;                  // cos(pi - fa)
    }
}

// ---------------- prep_w: round-1 2-pass, column-range parameterized --------
__global__ void prep_w_kernel(const float* __restrict__ w, int o_base, int ncols) {
    int idx = blockIdx.x*blockDim.x + threadIdx.x;
    int k = idx / ncols, ol = idx - k*ncols;
    int o = o_base + ol;
    __half* wh = (__half*)g_wh4;
    size_t base = (size_t)k*IN_SZ*OUTP + o;
    if (o >= OUT_SZ) {
        for (int f = 0; f < IN_SZ; f++) wh[base + (size_t)f*OUTP] = __float2half(0.f);
        return;
    }
    const float* col = w + (size_t)k*IN_SZ*OUT_SZ + o;
    float s = 0.f;
    #pragma unroll 8
    for (int f = 0; f < IN_SZ; f++) { float v = col[(size_t)f*OUT_SZ]; s += v*v; }
    float rinv = 1.f / fmaxf(sqrtf(s), 1e-12f);
    #pragma unroll 8
    for (int f = 0; f < IN_SZ; f++)
        wh[base + (size_t)f*OUTP] = __float2half(col[(size_t)f*OUT_SZ] * rinv);
}

// ---------------- GEMM helpers (round-1 verbatim) ---------------------------
__device__ __forceinline__ void cp_async16(uint32_t saddr, const void* gptr) {
    asm volatile("cp.async.cg.shared.global [%0], [%1], 16;\n" :: "r"(saddr), "l"(gptr));
}
#define CP_COMMIT() asm volatile("cp.async.commit_group;\n")
#define CP_WAIT1()  asm volatile("cp.async.wait_group 1;\n")

#define LDSM_X4(r0,r1,r2,r3,addr) \
    asm volatile("ldmatrix.sync.aligned.m8n8.x4.shared.b16 {%0,%1,%2,%3}, [%4];" \
        : "=r"(r0),"=r"(r1),"=r"(r2),"=r"(r3) : "r"(addr))
#define LDSM_X4_T(r0,r1,r2,r3,addr) \
    asm volatile("ldmatrix.sync.aligned.m8n8.x4.trans.shared.b16 {%0,%1,%2,%3}, [%4];" \
        : "=r"(r0),"=r"(r1),"=r"(r2),"=r"(r3) : "r"(addr))
#define MMA16816(c0,c1,c2,c3,a0,a1,a2,a3,b0,b1) \
    asm volatile("mma.sync.aligned.m16n8k16.row.col.f32.f16.f16.f32 " \
        "{%0,%1,%2,%3},{%4,%5,%6,%7},{%8,%9},{%0,%1,%2,%3};" \
        : "+f"(c0),"+f"(c1),"+f"(c2),"+f"(c3) \
        : "r"(a0),"r"(a1),"r"(a2),"r"(a3),"r"(b0),"r"(b1))

__device__ __forceinline__ void load_b_tile(__half* Bs, const __half* wh,
                                            int tid, int n0, int kc, int buf) {
    int chunk = tid & 15, r0 = tid >> 4;
    const __half* src = wh + (size_t)kc*IN_SZ*OUTP + n0;
    __half* dst = Bs + buf*BTILE;
    #pragma unroll
    for (int it = 0; it < 8; it++) {
        int row = it*16 + r0;
        cp_async16((uint32_t)__cvta_generic_to_shared(dst + row*LDB + chunk*8),
                   src + (size_t)row*OUTP + chunk*8);
    }
}

// ---------------- main GEMM (round-1 mainloop, half2 epilogue) ---------------
__global__ void __launch_bounds__(256, 1) gemm_kernel(int nt0) {
    extern __shared__ __half sm[];
    __half* As = sm;
    __half* Bs = sm + ATILE;
    const __half* xh = (const __half*)g_xh4;
    const __half* wh = (const __half*)g_wh4;

    int tid = threadIdx.x;
    int n0 = (nt0 + blockIdx.x) * 128;
    int m0 = blockIdx.y * 128;

    {
        int chunk = tid & 15, r0 = tid >> 4;
        #pragma unroll
        for (int it = 0; it < 8; it++) {
            int row = it*16 + r0;
            cp_async16((uint32_t)__cvta_generic_to_shared(As + row*LDA + chunk*8),
                       xh + (size_t)(m0 + row)*IN_SZ + chunk*8);
        }
    }
    load_b_tile(Bs, wh, tid, n0, 0, 0);
    CP_COMMIT();

    int wid = tid >> 5, lane = tid & 31;
    int wm = wid & 3, wn = wid >> 2;

    uint32_t smem_u32v = (uint32_t)__cvta_generic_to_shared(sm);
    uint32_t aA = smem_u32v + ((wm*32 + (lane & 15))*LDA + (lane >> 4)*8)*2;
    uint32_t aB = smem_u32v + ATILE*2 + ((lane & 15)*LDB + wn*64 + (lane >> 4)*8)*2;

    float mx[2][8][4];
    #pragma unroll
    for (int i = 0; i < 2; i++)
        #pragma unroll
        for (int j = 0; j < 8; j++)
            #pragma unroll
            for (int c = 0; c < 4; c++) mx[i][j][c] = -3.4e38f;

    for (int kc = 0; kc < KCEN; kc++) {
        int buf = kc & 1;
        if (kc < KCEN-1) load_b_tile(Bs, wh, tid, n0, kc+1, buf ^ 1);
        CP_COMMIT();
        CP_WAIT1();
        __syncthreads();

        float acc[2][8][4];
        #pragma unroll
        for (int i = 0; i < 2; i++)
            #pragma unroll
            for (int j = 0; j < 8; j++)
                #pragma unroll
                for (int c = 0; c < 4; c++) acc[i][j][c] = 0.f;

        #pragma unroll
        for (int ks = 0; ks < 8; ks++) {
            uint32_t a[2][4];
            #pragma unroll
            for (int mt = 0; mt < 2; mt++)
                LDSM_X4(a[mt][0], a[mt][1], a[mt][2], a[mt][3],
                        aA + mt*16*LDA*2 + ks*32);
            uint32_t bq[8][2];
            #pragma unroll
            for (int p = 0; p < 4; p++)
                LDSM_X4_T(bq[2*p][0], bq[2*p][1], bq[2*p+1][0], bq[2*p+1][1],
                          aB + buf*BTILE*2 + ks*16*LDB*2 + p*32);
            #pragma unroll
            for (int mt = 0; mt < 2; mt++)
                #pragma unroll
                for (int nt = 0; nt < 8; nt++)
                    MMA16816(acc[mt][nt][0], acc[mt][nt][1], acc[mt][nt][2], acc[mt][nt][3],
                             a[mt][0], a[mt][1], a[mt][2], a[mt][3],
                             bq[nt][0], bq[nt][1]);
        }
        #pragma unroll
        for (int i = 0; i < 2; i++)
            #pragma unroll
            for (int j = 0; j < 8; j++)
                #pragma unroll
                for (int c = 0; c < 4; c++)
                    mx[i][j][c] = fmaxf(mx[i][j][c], acc[i][j][c]);
        __syncthreads();
    }

    int rbase = m0 + wm*32 + (lane >> 2);
    int cbase = n0 + wn*64 + (lane & 3)*2;
    #pragma unroll
    for (int mt = 0; mt < 2; mt++)
        #pragma unroll
        for (int nt = 0; nt < 8; nt++) {
            int r = rbase + mt*16, c = cbase + nt*8;
            g_cosh[((size_t)r*OUTP + c) >> 1] =
                __floats2half2_rn(mx[mt][nt][0], mx[mt][nt][1]);
            g_cosh[((size_t)(r+8)*OUTP + c) >> 1] =
                __floats2half2_rn(mx[mt][nt][2], mx[mt][nt][3]);
        }
}

// ---------------- epilogue v3: half2 input, batched, 2-phase ----------------
__global__ void __launch_bounds__(256) epi_kernel(const int* __restrict__ label) {
    int r = blockIdx.x, t = threadIdx.x;     // 256 threads, 20 half2 each
    const __half2* row2 = g_cosh + (size_t)r*(OUTP/2);
    int lab = label[r];
    float cfa = g_cosfa[r], sfa = g_sinfa[r], cthr = g_costhr[r];

    __shared__ float s_mn[8], s_sum[8];
    __shared__ float s_lab;

    // phase 0: batched loads (high MLP)
    __half2 v2[20];
    #pragma unroll
    for (int j = 0; j < 20; j++)
        v2[j] = row2[j*256 + t];

    // phase 1: clip/scale, local max over non-label, exact margin for label
    const float CLO = -1.0f + 1e-6f, CHI = 1.0f - 1e-6f;
    float mnon = -3.0e38f;
    #pragma unroll
    for (int j = 0; j < 20; j++) {
        int i = j*256 + t;
        if (i < OUT_SZ/2) {
            float c0 = fminf(fmaxf(__low2float(v2[j]),  CLO), CHI);
            float c1 = fminf(fmaxf(__high2float(v2[j]), CLO), CHI);
            int o0 = 2*i, o1 = 2*i + 1;
            if (o0 == lab) {
                s_lab = (c0 >= cthr)
                    ? (c0*cfa - sqrtf(fmaxf(1.f - c0*c0, 0.f))*sfa) * SSC
                    : c0 * SSC;
            } else mnon = fmaxf(mnon, c0 * SSC);
            if (o1 == lab) {
                s_lab = (c1 >= cthr)
                    ? (c1*cfa - sqrtf(fmaxf(1.f - c1*c1, 0.f))*sfa) * SSC
                    : c1 * SSC;
            } else mnon = fmaxf(mnon, c1 * SSC);
        }
    }
    #pragma unroll
    for (int o = 16; o; o >>= 1) mnon = fmaxf(mnon, __shfl_xor_sync(0xffffffffu, mnon, o));
    if ((t & 31) == 0) s_mn[t >> 5] = mnon;
    __syncthreads();
    float Mn = fmaxf(fmaxf(fmaxf(s_mn[0], s_mn[1]), fmaxf(s_mn[2], s_mn[3])),
                     fmaxf(fmaxf(s_mn[4], s_mn[5]), fmaxf(s_mn[6], s_mn[7])));
    float llab = s_lab;
    float M = fmaxf(Mn, llab);

    // phase 2: independent expf sum
    float s = 0.f;
    #pragma unroll
    for (int j = 0; j < 20; j++) {
        int i = j*256 + t;
        if (i < OUT_SZ/2) {
            float c0 = fminf(fmaxf(__low2float(v2[j]),  CLO), CHI);
            float c1 = fminf(fmaxf(__high2float(v2[j]), CLO), CHI);
            float l0 = (2*i     == lab) ? llab : c0 * SSC;
            float l1 = (2*i + 1 == lab) ? llab : c1 * SSC;
            s += __expf(l0 - M) + __expf(l1 - M);
        }
    }
    #pragma unroll
    for (int o = 16; o; o >>= 1) s += __shfl_xor_sync(0xffffffffu, s, o);
    if ((t & 31) == 0) s_sum[t >> 5] = s;
    __syncthreads();
    if (t == 0) {
        float S = s_sum[0]+s_sum[1]+s_sum[2]+s_sum[3]
                + s_sum[4]+s_sum[5]+s_sum[6]+s_sum[7];
        g_loss[r] = logf(S) + M - llab;
        g_corr[r] = (llab > Mn) ? 1.f : 0.f;
    }
}

// ---------------- final reduction ------------------------------------------
__global__ void fin_kernel(float* __restrict__ out) {
    int t = threadIdx.x;                     // 1024 threads
    __shared__ float sl[1024], sc[1024];
    sl[t] = g_loss[t]; sc[t] = g_corr[t];
    __syncthreads();
    for (int st = 512; st > 0; st >>= 1) {
        if (t < st) { sl[t] += sl[t+st]; sc[t] += sc[t+st]; }
        __syncthreads();
    }
    if (t == 0) {
        out[0] = sl[0] * (1.f/1024.f);
        out[1] = sc[0] * (100.f/1024.f);
    }
}

// ---------------- launch: fork/join overlap of prep_w tail with GEMM head ---
extern "C" void kernel_launch(void* const* d_in, const int* in_sizes, int n_in,
                              void* d_out, int out_size) {
    const float* x      = (const float*)d_in[0];
    const float* factor = (const float*)d_in[1];
    const int*   label  = (const int*)  d_in[2];
    const float* w      = (const float*)d_in[3];
    float* out = (float*)d_out;

    cudaFuncSetAttribute(gemm_kernel, cudaFuncAttributeMaxDynamicSharedMemorySize, SMEM_BYTES);

    cudaStream_t s1;
    cudaStreamCreateWithFlags(&s1, cudaStreamNonBlocking);
    cudaEvent_t eFork, eJoin;
    cudaEventCreateWithFlags(&eFork, cudaEventDisableTiming);
    cudaEventCreateWithFlags(&eJoin, cudaEventDisableTiming);

    // fork: prep_w tail (n-tiles NT1..78 incl. pad) on s1, concurrent with head
    cudaEventRecord(eFork, 0);
    cudaStreamWaitEvent(s1, eFork, 0);
    {
        int ncols2 = (NT - NT1) * 128;                 // 8064 (incl. pad cols)
        prep_w_kernel<<<(KCEN*ncols2)/256, 256, 0, s1>>>(w, NT1*128, ncols2);
    }

    // head on default stream
    prep_x_kernel<<<B_SZ, 128>>>(x, factor);
    prep_w_kernel<<<(KCEN*NT1*128)/256, 256>>>(w, 0, NT1*128);
    gemm_kernel<<<dim3(NT1, B_SZ/128), 256, SMEM_BYTES>>>(0);

    // join: remaining GEMM needs prep_w tail
    cudaEventRecord(eJoin, s1);
    cudaStreamWaitEvent(0, eJoin, 0);
    gemm_kernel<<<dim3(NT - NT1, B_SZ/128), 256, SMEM_BYTES>>>(NT1);

    epi_kernel<<<B_SZ, 256>>>(label);
    fin_kernel<<<1, 1024>>>(out);

    cudaStreamDestroy(s1);
    cudaEventDestroy(eFork);
    cudaEventDestroy(eJoin);
}

// round 9
// speedup vs baseline: 1.3715x; 1.1014x over previous
#include <cuda_runtime.h>
#include <cuda_fp16.h>
#include <cstdint>

#define B_SZ   1024
#define IN_SZ  128
#define OUT_SZ 10000
#define OUTP   10112            // 158 * 64, padded
#define KCEN   16
#define NT64   158              // n-tiles of 64 cols
#define NT1    32               // n-tiles (64-wide) in first GEMM chunk
#define SSC    64.0f

#define LDA 136                 // A pitch (halves): 128 + 8
#define LDB 72                  // B pitch (halves): 64 + 8
#define ATILE (128*LDA)
#define BTILE (128*LDB)
#define SMEM_HALVES (ATILE + 2*BTILE)
#define SMEM_BYTES  (SMEM_HALVES*2)      // 71680

// ---------------- device scratch ----------------
__device__ float4  g_xh4[(B_SZ*IN_SZ)/8];                      // 256 KB fp16
__device__ float4  g_wh4[((size_t)KCEN*IN_SZ*OUTP)/8];         // 41.4 MB fp16 (normalized)
__device__ __half2 g_cosh[((size_t)B_SZ*OUTP)/2 + 256];        // 20.7 MB fp16 cos (+pad)
__device__ float   g_cosfa[B_SZ], g_sinfa[B_SZ], g_costhr[B_SZ];
__device__ float   g_loss[B_SZ], g_corr[B_SZ];

// ---------------- prep_x ------------------------------------------------------
__global__ void prep_x_kernel(const float* __restrict__ x,
                              const float* __restrict__ factor) {
    int b = blockIdx.x, f = threadIdx.x;     // 128 threads
    float v = x[b*IN_SZ + f];
    float s = v*v;
    #pragma unroll
    for (int o = 16; o; o >>= 1) s += __shfl_xor_sync(0xffffffffu, s, o);
    __shared__ float ws[4];
    if ((f & 31) == 0) ws[f >> 5] = s;
    __syncthreads();
    float tot = ws[0] + ws[1] + ws[2] + ws[3];
    float rinv = 1.f / fmaxf(sqrtf(tot), 1e-12f);
    ((__half*)g_xh4)[b*IN_SZ + f] = __float2half(v * rinv);
    if (f == 0) {
        float fa = powf(1.5f, factor[b] * (1.f/12.f)) * 0.5f;
        float cfa = cosf(fa);
        g_cosfa[b] = cfa;
        g_sinfa[b] = sinf(fa);
        g_costhr[b] = -cfa;                  // cos(pi - fa)
    }
}

// ---------------- prep_w: 2-pass, column-range parameterized ------------------
__global__ void prep_w_kernel(const float* __restrict__ w, int o_base, int ncols) {
    int idx = blockIdx.x*blockDim.x + threadIdx.x;
    int k = idx / ncols, ol = idx - k*ncols;
    int o = o_base + ol;
    __half* wh = (__half*)g_wh4;
    size_t base = (size_t)k*IN_SZ*OUTP + o;
    if (o >= OUT_SZ) {
        for (int f = 0; f < IN_SZ; f++) wh[base + (size_t)f*OUTP] = __float2half(0.f);
        return;
    }
    const float* col = w + (size_t)k*IN_SZ*OUT_SZ + o;
    float s = 0.f;
    #pragma unroll 8
    for (int f = 0; f < IN_SZ; f++) { float v = col[(size_t)f*OUT_SZ]; s += v*v; }
    float rinv = 1.f / fmaxf(sqrtf(s), 1e-12f);
    #pragma unroll 8
    for (int f = 0; f < IN_SZ; f++)
        wh[base + (size_t)f*OUTP] = __float2half(col[(size_t)f*OUT_SZ] * rinv);
}

// ---------------- GEMM helpers -------------------------------------------------
__device__ __forceinline__ void cp_async16(uint32_t saddr, const void* gptr) {
    asm volatile("cp.async.cg.shared.global [%0], [%1], 16;\n" :: "r"(saddr), "l"(gptr));
}
#define CP_COMMIT() asm volatile("cp.async.commit_group;\n")
#define CP_WAIT1()  asm volatile("cp.async.wait_group 1;\n")

#define LDSM_X4(r0,r1,r2,r3,addr) \
    asm volatile("ldmatrix.sync.aligned.m8n8.x4.shared.b16 {%0,%1,%2,%3}, [%4];" \
        : "=r"(r0),"=r"(r1),"=r"(r2),"=r"(r3) : "r"(addr))
#define LDSM_X4_T(r0,r1,r2,r3,addr) \
    asm volatile("ldmatrix.sync.aligned.m8n8.x4.trans.shared.b16 {%0,%1,%2,%3}, [%4];" \
        : "=r"(r0),"=r"(r1),"=r"(r2),"=r"(r3) : "r"(addr))
#define MMA16816(c0,c1,c2,c3,a0,a1,a2,a3,b0,b1) \
    asm volatile("mma.sync.aligned.m16n8k16.row.col.f32.f16.f16.f32 " \
        "{%0,%1,%2,%3},{%4,%5,%6,%7},{%8,%9},{%0,%1,%2,%3};" \
        : "+f"(c0),"+f"(c1),"+f"(c2),"+f"(c3) \
        : "r"(a0),"r"(a1),"r"(a2),"r"(a3),"r"(b0),"r"(b1))

// B tile: 128 k-rows x 64 n-cols = 8 chunks of 16B per row (FIXED)
__device__ __forceinline__ void load_b_tile(__half* Bs, const __half* wh,
                                            int tid, int n0, int kc, int buf) {
    int chunk = tid & 7, r0 = tid >> 3;          // 32 rows per pass of 256 thr
    const __half* src = wh + (size_t)kc*IN_SZ*OUTP + n0;
    __half* dst = Bs + buf*BTILE;
    #pragma unroll
    for (int it = 0; it < 4; it++) {
        int row = it*32 + r0;
        cp_async16((uint32_t)__cvta_generic_to_shared(dst + row*LDB + chunk*8),
                   src + (size_t)row*OUTP + chunk*8);
    }
}

// ---------------- main GEMM: 128x64 CTA tile, 2 CTAs/SM -----------------------
__global__ void __launch_bounds__(256, 2) gemm_kernel(int nt0) {
    extern __shared__ __half sm[];
    __half* As = sm;
    __half* Bs = sm + ATILE;
    const __half* xh = (const __half*)g_xh4;
    const __half* wh = (const __half*)g_wh4;

    int tid = threadIdx.x;
    int n0 = (nt0 + blockIdx.x) * 64;
    int m0 = blockIdx.y * 128;

    {   // A tile: 128x128 halves
        int chunk = tid & 15, r0 = tid >> 4;
        #pragma unroll
        for (int it = 0; it < 8; it++) {
            int row = it*16 + r0;
            cp_async16((uint32_t)__cvta_generic_to_shared(As + row*LDA + chunk*8),
                       xh + (size_t)(m0 + row)*IN_SZ + chunk*8);
        }
    }
    load_b_tile(Bs, wh, tid, n0, 0, 0);
    CP_COMMIT();

    int wid = tid >> 5, lane = tid & 31;
    int wm = wid & 3, wn = wid >> 2;             // 4 m-warps x 2 n-warps (32x32 each)

    uint32_t smem_u32v = (uint32_t)__cvta_generic_to_shared(sm);
    uint32_t aA = smem_u32v + ((wm*32 + (lane & 15))*LDA + (lane >> 4)*8)*2;
    uint32_t aB = smem_u32v + ATILE*2 + ((lane & 15)*LDB + wn*32 + (lane >> 4)*8)*2;

    float mx[2][4][4];
    #pragma unroll
    for (int i = 0; i < 2; i++)
        #pragma unroll
        for (int j = 0; j < 4; j++)
            #pragma unroll
            for (int c = 0; c < 4; c++) mx[i][j][c] = -3.4e38f;

    for (int kc = 0; kc < KCEN; kc++) {
        int buf = kc & 1;
        if (kc < KCEN-1) load_b_tile(Bs, wh, tid, n0, kc+1, buf ^ 1);
        CP_COMMIT();
        CP_WAIT1();
        __syncthreads();

        float acc[2][4][4];
        #pragma unroll
        for (int i = 0; i < 2; i++)
            #pragma unroll
            for (int j = 0; j < 4; j++)
                #pragma unroll
                for (int c = 0; c < 4; c++) acc[i][j][c] = 0.f;

        #pragma unroll
        for (int ks = 0; ks < 8; ks++) {
            uint32_t a[2][4];
            #pragma unroll
            for (int mt = 0; mt < 2; mt++)
                LDSM_X4(a[mt][0], a[mt][1], a[mt][2], a[mt][3],
                        aA + mt*16*LDA*2 + ks*32);
            uint32_t bq[4][2];
            #pragma unroll
            for (int p = 0; p < 2; p++)
                LDSM_X4_T(bq[2*p][0], bq[2*p][1], bq[2*p+1][0], bq[2*p+1][1],
                          aB + buf*BTILE*2 + ks*16*LDB*2 + p*32);
            #pragma unroll
            for (int mt = 0; mt < 2; mt++)
                #pragma unroll
                for (int nt = 0; nt < 4; nt++)
                    MMA16816(acc[mt][nt][0], acc[mt][nt][1], acc[mt][nt][2], acc[mt][nt][3],
                             a[mt][0], a[mt][1], a[mt][2], a[mt][3],
                             bq[nt][0], bq[nt][1]);
        }
        #pragma unroll
        for (int i = 0; i < 2; i++)
            #pragma unroll
            for (int j = 0; j < 4; j++)
                #pragma unroll
                for (int c = 0; c < 4; c++)
                    mx[i][j][c] = fmaxf(mx[i][j][c], acc[i][j][c]);
        __syncthreads();
    }

    int rbase = m0 + wm*32 + (lane >> 2);
    int cbase = n0 + wn*32 + (lane & 3)*2;
    #pragma unroll
    for (int mt = 0; mt < 2; mt++)
        #pragma unroll
        for (int nt = 0; nt < 4; nt++) {
            int r = rbase + mt*16, c = cbase + nt*8;
            g_cosh[((size_t)r*OUTP + c) >> 1] =
                __floats2half2_rn(mx[mt][nt][0], mx[mt][nt][1]);
            g_cosh[((size_t)(r+8)*OUTP + c) >> 1] =
                __floats2half2_rn(mx[mt][nt][2], mx[mt][nt][3]);
        }
}

// ---------------- epilogue: half2 input, batched, 2-phase ----------------------
__global__ void __launch_bounds__(256) epi_kernel(const int* __restrict__ label) {
    int r = blockIdx.x, t = threadIdx.x;     // 256 threads, 20 half2 each
    const __half2* row2 = g_cosh + (size_t)r*(OUTP/2);
    int lab = label[r];
    float cfa = g_cosfa[r], sfa = g_sinfa[r], cthr = g_costhr[r];

    __shared__ float s_mn[8], s_sum[8];
    __shared__ float s_lab;

    __half2 v2[20];
    #pragma unroll
    for (int j = 0; j < 20; j++)
        v2[j] = row2[j*256 + t];

    const float CLO = -1.0f + 1e-6f, CHI = 1.0f - 1e-6f;
    float mnon = -3.0e38f;
    #pragma unroll
    for (int j = 0; j < 20; j++) {
        int i = j*256 + t;
        if (i < OUT_SZ/2) {
            float c0 = fminf(fmaxf(__low2float(v2[j]),  CLO), CHI);
            float c1 = fminf(fmaxf(__high2float(v2[j]), CLO), CHI);
            int o0 = 2*i, o1 = 2*i + 1;
            if (o0 == lab) {
                s_lab = (c0 >= cthr)
                    ? (c0*cfa - sqrtf(fmaxf(1.f - c0*c0, 0.f))*sfa) * SSC
                    : c0 * SSC;
            } else mnon = fmaxf(mnon, c0 * SSC);
            if (o1 == lab) {
                s_lab = (c1 >= cthr)
                    ? (c1*cfa - sqrtf(fmaxf(1.f - c1*c1, 0.f))*sfa) * SSC
                    : c1 * SSC;
            } else mnon = fmaxf(mnon, c1 * SSC);
        }
    }
    #pragma unroll
    for (int o = 16; o; o >>= 1) mnon = fmaxf(mnon, __shfl_xor_sync(0xffffffffu, mnon, o));
    if ((t & 31) == 0) s_mn[t >> 5] = mnon;
    __syncthreads();
    float Mn = fmaxf(fmaxf(fmaxf(s_mn[0], s_mn[1]), fmaxf(s_mn[2], s_mn[3])),
                     fmaxf(fmaxf(s_mn[4], s_mn[5]), fmaxf(s_mn[6], s_mn[7])));
    float llab = s_lab;
    float M = fmaxf(Mn, llab);

    float s = 0.f;
    #pragma unroll
    for (int j = 0; j < 20; j++) {
        int i = j*256 + t;
        if (i < OUT_SZ/2) {
            float c0 = fminf(fmaxf(__low2float(v2[j]),  CLO), CHI);
            float c1 = fminf(fmaxf(__high2float(v2[j]), CLO), CHI);
            float l0 = (2*i     == lab) ? llab : c0 * SSC;
            float l1 = (2*i + 1 == lab) ? llab : c1 * SSC;
            s += __expf(l0 - M) + __expf(l1 - M);
        }
    }
    #pragma unroll
    for (int o = 16; o; o >>= 1) s += __shfl_xor_sync(0xffffffffu, s, o);
    if ((t & 31) == 0) s_sum[t >> 5] = s;
    __syncthreads();
    if (t == 0) {
        float S = s_sum[0]+s_sum[1]+s_sum[2]+s_sum[3]
                + s_sum[4]+s_sum[5]+s_sum[6]+s_sum[7];
        g_loss[r] = logf(S) + M - llab;
        g_corr[r] = (llab > Mn) ? 1.f : 0.f;
    }
}

// ---------------- final reduction ------------------------------------------
__global__ void fin_kernel(float* __restrict__ out) {
    int t = threadIdx.x;                     // 1024 threads
    __shared__ float sl[1024], sc[1024];
    sl[t] = g_loss[t]; sc[t] = g_corr[t];
    __syncthreads();
    for (int st = 512; st > 0; st >>= 1) {
        if (t < st) { sl[t] += sl[t+st]; sc[t] += sc[t+st]; }
        __syncthreads();
    }
    if (t == 0) {
        out[0] = sl[0] * (1.f/1024.f);
        out[1] = sc[0] * (100.f/1024.f);
    }
}

// ---------------- launch: fork/join overlap of prep_w tail with GEMM head ---
extern "C" void kernel_launch(void* const* d_in, const int* in_sizes, int n_in,
                              void* d_out, int out_size) {
    const float* x      = (const float*)d_in[0];
    const float* factor = (const float*)d_in[1];
    const int*   label  = (const int*)  d_in[2];
    const float* w      = (const float*)d_in[3];
    float* out = (float*)d_out;

    cudaFuncSetAttribute(gemm_kernel, cudaFuncAttributeMaxDynamicSharedMemorySize, SMEM_BYTES);

    cudaStream_t s1;
    cudaStreamCreateWithFlags(&s1, cudaStreamNonBlocking);
    cudaEvent_t eFork, eJoin;
    cudaEventCreateWithFlags(&eFork, cudaEventDisableTiming);
    cudaEventCreateWithFlags(&eJoin, cudaEventDisableTiming);

    // fork: prep_w tail (cols NT1*64 .. OUTP) on s1, concurrent with head
    cudaEventRecord(eFork, 0);
    cudaStreamWaitEvent(s1, eFork, 0);
    {
        int ncols2 = (NT64 - NT1) * 64;               // 8064 (incl. pad cols)
        prep_w_kernel<<<(KCEN*ncols2)/256, 256, 0, s1>>>(w, NT1*64, ncols2);
    }

    // head on default stream
    prep_x_kernel<<<B_SZ, 128>>>(x, factor);
    prep_w_kernel<<<(KCEN*NT1*64)/256, 256>>>(w, 0, NT1*64);
    gemm_kernel<<<dim3(NT1, B_SZ/128), 256, SMEM_BYTES>>>(0);

    // join: remaining GEMM needs prep_w tail
    cudaEventRecord(eJoin, s1);
    cudaStreamWaitEvent(0, eJoin, 0);
    gemm_kernel<<<dim3(NT64 - NT1, B_SZ/128), 256, SMEM_BYTES>>>(NT1);

    epi_kernel<<<B_SZ, 256>>>(label);
    fin_kernel<<<1, 1024>>>(out);

    cudaStreamDestroy(s1);
    cudaEventDestroy(eFork);
    cudaEventDestroy(eJoin);
}

// round 10
// speedup vs baseline: 1.4010x; 1.0215x over previous
#include <cuda_runtime.h>
#include <cuda_fp16.h>
#include <cstdint>

#define B_SZ   1024
#define IN_SZ  128
#define OUT_SZ 10000
#define OUTP   10112            // 158 * 64, padded
#define KCEN   16
#define NT64   158              // n-tiles of 64 cols
#define NT1    32               // n-tiles (64-wide) in first GEMM chunk
#define SSC    64.0f

#define LDA 136                 // A pitch (halves): 128 + 8
#define LDB 72                  // B pitch (halves): 64 + 8
#define ATILE (128*LDA)
#define BTILE (128*LDB)
#define SMEM_HALVES (ATILE + 2*BTILE)
#define SMEM_BYTES  (SMEM_HALVES*2)      // 71680

// ---------------- device scratch ----------------
__device__ float4  g_xh4[(B_SZ*IN_SZ)/8];                      // 256 KB fp16
__device__ float4  g_wh4[((size_t)KCEN*IN_SZ*OUTP)/8];         // 41.4 MB fp16 (normalized)
__device__ __half2 g_cosh[((size_t)B_SZ*OUTP)/2 + 256];        // 20.7 MB fp16 cos (+pad)
__device__ float   g_cosfa[B_SZ], g_sinfa[B_SZ], g_costhr[B_SZ];
__device__ float   g_loss[B_SZ], g_corr[B_SZ];

// ---------------- prep_x ------------------------------------------------------
__global__ void prep_x_kernel(const float* __restrict__ x,
                              const float* __restrict__ factor) {
    int b = blockIdx.x, f = threadIdx.x;     // 128 threads
    float v = x[b*IN_SZ + f];
    float s = v*v;
    #pragma unroll
    for (int o = 16; o; o >>= 1) s += __shfl_xor_sync(0xffffffffu, s, o);
    __shared__ float ws[4];
    if ((f & 31) == 0) ws[f >> 5] = s;
    __syncthreads();
    float tot = ws[0] + ws[1] + ws[2] + ws[3];
    float rinv = 1.f / fmaxf(sqrtf(tot), 1e-12f);
    ((__half*)g_xh4)[b*IN_SZ + f] = __float2half(v * rinv);
    if (f == 0) {
        float fa = powf(1.5f, factor[b] * (1.f/12.f)) * 0.5f;
        float cfa = cosf(fa);
        g_cosfa[b] = cfa;
        g_sinfa[b] = sinf(fa);
        g_costhr[b] = -cfa;                  // cos(pi - fa)
    }
}

// ---------------- prep_w: 2-pass, column-range parameterized ------------------
__global__ void prep_w_kernel(const float* __restrict__ w, int o_base, int ncols) {
    int idx = blockIdx.x*blockDim.x + threadIdx.x;
    int k = idx / ncols, ol = idx - k*ncols;
    int o = o_base + ol;
    __half* wh = (__half*)g_wh4;
    size_t base = (size_t)k*IN_SZ*OUTP + o;
    if (o >= OUT_SZ) {
        for (int f = 0; f < IN_SZ; f++) wh[base + (size_t)f*OUTP] = __float2half(0.f);
        return;
    }
    const float* col = w + (size_t)k*IN_SZ*OUT_SZ + o;
    float s = 0.f;
    #pragma unroll 8
    for (int f = 0; f < IN_SZ; f++) { float v = col[(size_t)f*OUT_SZ]; s += v*v; }
    float rinv = 1.f / fmaxf(sqrtf(s), 1e-12f);
    #pragma unroll 8
    for (int f = 0; f < IN_SZ; f++)
        wh[base + (size_t)f*OUTP] = __float2half(col[(size_t)f*OUT_SZ] * rinv);
}

// ---------------- GEMM helpers -------------------------------------------------
__device__ __forceinline__ void cp_async16(uint32_t saddr, const void* gptr) {
    asm volatile("cp.async.cg.shared.global [%0], [%1], 16;\n" :: "r"(saddr), "l"(gptr));
}
#define CP_COMMIT() asm volatile("cp.async.commit_group;\n")
#define CP_WAIT1()  asm volatile("cp.async.wait_group 1;\n")

#define LDSM_X4(r0,r1,r2,r3,addr) \
    asm volatile("ldmatrix.sync.aligned.m8n8.x4.shared.b16 {%0,%1,%2,%3}, [%4];" \
        : "=r"(r0),"=r"(r1),"=r"(r2),"=r"(r3) : "r"(addr))
#define LDSM_X4_T(r0,r1,r2,r3,addr) \
    asm volatile("ldmatrix.sync.aligned.m8n8.x4.trans.shared.b16 {%0,%1,%2,%3}, [%4];" \
        : "=r"(r0),"=r"(r1),"=r"(r2),"=r"(r3) : "r"(addr))
#define MMA16816(c0,c1,c2,c3,a0,a1,a2,a3,b0,b1) \
    asm volatile("mma.sync.aligned.m16n8k16.row.col.f32.f16.f16.f32 " \
        "{%0,%1,%2,%3},{%4,%5,%6,%7},{%8,%9},{%0,%1,%2,%3};" \
        : "+f"(c0),"+f"(c1),"+f"(c2),"+f"(c3) \
        : "r"(a0),"r"(a1),"r"(a2),"r"(a3),"r"(b0),"r"(b1))

// B tile: 128 k-rows x 64 n-cols = 8 chunks of 16B per row
__device__ __forceinline__ void load_b_tile(__half* Bs, const __half* wh,
                                            int tid, int n0, int kc, int buf) {
    int chunk = tid & 7, r0 = tid >> 3;          // 32 rows per pass of 256 thr
    const __half* src = wh + (size_t)kc*IN_SZ*OUTP + n0;
    __half* dst = Bs + buf*BTILE;
    #pragma unroll
    for (int it = 0; it < 4; it++) {
        int row = it*32 + r0;
        cp_async16((uint32_t)__cvta_generic_to_shared(dst + row*LDB + chunk*8),
                   src + (size_t)row*OUTP + chunk*8);
    }
}

// ---------------- main GEMM: 128x64 tile, 2 CTA/SM, reg-pipelined frags -------
__global__ void __launch_bounds__(256, 2) gemm_kernel(int nt0) {
    extern __shared__ __half sm[];
    __half* As = sm;
    __half* Bs = sm + ATILE;
    const __half* xh = (const __half*)g_xh4;
    const __half* wh = (const __half*)g_wh4;

    int tid = threadIdx.x;
    int n0 = (nt0 + blockIdx.x) * 64;
    int m0 = blockIdx.y * 128;

    {   // A tile: 128x128 halves
        int chunk = tid & 15, r0 = tid >> 4;
        #pragma unroll
        for (int it = 0; it < 8; it++) {
            int row = it*16 + r0;
            cp_async16((uint32_t)__cvta_generic_to_shared(As + row*LDA + chunk*8),
                       xh + (size_t)(m0 + row)*IN_SZ + chunk*8);
        }
    }
    load_b_tile(Bs, wh, tid, n0, 0, 0);
    CP_COMMIT();

    int wid = tid >> 5, lane = tid & 31;
    int wm = wid & 3, wn = wid >> 2;             // 4 m-warps x 2 n-warps (32x32 each)

    uint32_t smem_u32v = (uint32_t)__cvta_generic_to_shared(sm);
    uint32_t aA = smem_u32v + ((wm*32 + (lane & 15))*LDA + (lane >> 4)*8)*2;
    uint32_t aB = smem_u32v + ATILE*2 + ((lane & 15)*LDB + wn*32 + (lane >> 4)*8)*2;

    // running max held in fp16 pairs: [mt][nt][0]=rows(r,c|c+1), [1]=rows(r+8)
    __half2 mx2[2][4][2];
    const __half2 NEGH = __floats2half2_rn(-65504.f, -65504.f);
    #pragma unroll
    for (int i = 0; i < 2; i++)
        #pragma unroll
        for (int j = 0; j < 4; j++) { mx2[i][j][0] = NEGH; mx2[i][j][1] = NEGH; }

    for (int kc = 0; kc < KCEN; kc++) {
        int buf = kc & 1;
        if (kc < KCEN-1) load_b_tile(Bs, wh, tid, n0, kc+1, buf ^ 1);
        CP_COMMIT();
        CP_WAIT1();
        __syncthreads();

        uint32_t bbase = aB + buf*BTILE*2;

        float acc[2][4][4];
        #pragma unroll
        for (int i = 0; i < 2; i++)
            #pragma unroll
            for (int j = 0; j < 4; j++)
                #pragma unroll
                for (int c = 0; c < 4; c++) acc[i][j][c] = 0.f;

        // register-double-buffered fragments
        uint32_t a[2][2][4], bq[2][4][2];
        // prologue: load ks=0 into buffer 0
        #pragma unroll
        for (int mt = 0; mt < 2; mt++)
            LDSM_X4(a[0][mt][0], a[0][mt][1], a[0][mt][2], a[0][mt][3],
                    aA + mt*16*LDA*2);
        #pragma unroll
        for (int p = 0; p < 2; p++)
            LDSM_X4_T(bq[0][2*p][0], bq[0][2*p][1], bq[0][2*p+1][0], bq[0][2*p+1][1],
                      bbase + p*32);

        #pragma unroll
        for (int ks = 0; ks < 8; ks++) {
            int cur = ks & 1, nxt = cur ^ 1;
            if (ks < 7) {
                #pragma unroll
                for (int mt = 0; mt < 2; mt++)
                    LDSM_X4(a[nxt][mt][0], a[nxt][mt][1], a[nxt][mt][2], a[nxt][mt][3],
                            aA + mt*16*LDA*2 + (ks+1)*32);
                #pragma unroll
                for (int p = 0; p < 2; p++)
                    LDSM_X4_T(bq[nxt][2*p][0], bq[nxt][2*p][1],
                              bq[nxt][2*p+1][0], bq[nxt][2*p+1][1],
                              bbase + (ks+1)*16*LDB*2 + p*32);
            }
            #pragma unroll
            for (int mt = 0; mt < 2; mt++)
                #pragma unroll
                for (int nt = 0; nt < 4; nt++)
                    MMA16816(acc[mt][nt][0], acc[mt][nt][1], acc[mt][nt][2], acc[mt][nt][3],
                             a[cur][mt][0], a[cur][mt][1], a[cur][mt][2], a[cur][mt][3],
                             bq[cur][nt][0], bq[cur][nt][1]);
        }

        #pragma unroll
        for (int i = 0; i < 2; i++)
            #pragma unroll
            for (int j = 0; j < 4; j++) {
                mx2[i][j][0] = __hmax2(mx2[i][j][0],
                                       __floats2half2_rn(acc[i][j][0], acc[i][j][1]));
                mx2[i][j][1] = __hmax2(mx2[i][j][1],
                                       __floats2half2_rn(acc[i][j][2], acc[i][j][3]));
            }
        __syncthreads();
    }

    int rbase = m0 + wm*32 + (lane >> 2);
    int cbase = n0 + wn*32 + (lane & 3)*2;
    #pragma unroll
    for (int mt = 0; mt < 2; mt++)
        #pragma unroll
        for (int nt = 0; nt < 4; nt++) {
            int r = rbase + mt*16, c = cbase + nt*8;
            g_cosh[((size_t)r*OUTP + c) >> 1]     = mx2[mt][nt][0];
            g_cosh[((size_t)(r+8)*OUTP + c) >> 1] = mx2[mt][nt][1];
        }
}

// ---------------- epilogue: half2 input, batched, 2-phase ----------------------
__global__ void __launch_bounds__(256) epi_kernel(const int* __restrict__ label) {
    int r = blockIdx.x, t = threadIdx.x;     // 256 threads, 20 half2 each
    const __half2* row2 = g_cosh + (size_t)r*(OUTP/2);
    int lab = label[r];
    float cfa = g_cosfa[r], sfa = g_sinfa[r], cthr = g_costhr[r];

    __shared__ float s_mn[8], s_sum[8];
    __shared__ float s_lab;

    __half2 v2[20];
    #pragma unroll
    for (int j = 0; j < 20; j++)
        v2[j] = row2[j*256 + t];

    const float CLO = -1.0f + 1e-6f, CHI = 1.0f - 1e-6f;
    float mnon = -3.0e38f;
    #pragma unroll
    for (int j = 0; j < 20; j++) {
        int i = j*256 + t;
        if (i < OUT_SZ/2) {
            float c0 = fminf(fmaxf(__low2float(v2[j]),  CLO), CHI);
            float c1 = fminf(fmaxf(__high2float(v2[j]), CLO), CHI);
            int o0 = 2*i, o1 = 2*i + 1;
            if (o0 == lab) {
                s_lab = (c0 >= cthr)
                    ? (c0*cfa - sqrtf(fmaxf(1.f - c0*c0, 0.f))*sfa) * SSC
                    : c0 * SSC;
            } else mnon = fmaxf(mnon, c0 * SSC);
            if (o1 == lab) {
                s_lab = (c1 >= cthr)
                    ? (c1*cfa - sqrtf(fmaxf(1.f - c1*c1, 0.f))*sfa) * SSC
                    : c1 * SSC;
            } else mnon = fmaxf(mnon, c1 * SSC);
        }
    }
    #pragma unroll
    for (int o = 16; o; o >>= 1) mnon = fmaxf(mnon, __shfl_xor_sync(0xffffffffu, mnon, o));
    if ((t & 31) == 0) s_mn[t >> 5] = mnon;
    __syncthreads();
    float Mn = fmaxf(fmaxf(fmaxf(s_mn[0], s_mn[1]), fmaxf(s_mn[2], s_mn[3])),
                     fmaxf(fmaxf(s_mn[4], s_mn[5]), fmaxf(s_mn[6], s_mn[7])));
    float llab = s_lab;
    float M = fmaxf(Mn, llab);

    float s = 0.f;
    #pragma unroll
    for (int j = 0; j < 20; j++) {
        int i = j*256 + t;
        if (i < OUT_SZ/2) {
            float c0 = fminf(fmaxf(__low2float(v2[j]),  CLO), CHI);
            float c1 = fminf(fmaxf(__high2float(v2[j]), CLO), CHI);
            float l0 = (2*i     == lab) ? llab : c0 * SSC;
            float l1 = (2*i + 1 == lab) ? llab : c1 * SSC;
            s += __expf(l0 - M) + __expf(l1 - M);
        }
    }
    #pragma unroll
    for (int o = 16; o; o >>= 1) s += __shfl_xor_sync(0xffffffffu, s, o);
    if ((t & 31) == 0) s_sum[t >> 5] = s;
    __syncthreads();
    if (t == 0) {
        float S = s_sum[0]+s_sum[1]+s_sum[2]+s_sum[3]
                + s_sum[4]+s_sum[5]+s_sum[6]+s_sum[7];
        g_loss[r] = logf(S) + M - llab;
        g_corr[r] = (llab > Mn) ? 1.f : 0.f;
    }
}

// ---------------- final reduction ------------------------------------------
__global__ void fin_kernel(float* __restrict__ out) {
    int t = threadIdx.x;                     // 1024 threads
    __shared__ float sl[1024], sc[1024];
    sl[t] = g_loss[t]; sc[t] = g_corr[t];
    __syncthreads();
    for (int st = 512; st > 0; st >>= 1) {
        if (t < st) { sl[t] += sl[t+st]; sc[t] += sc[t+st]; }
        __syncthreads();
    }
    if (t == 0) {
        out[0] = sl[0] * (1.f/1024.f);
        out[1] = sc[0] * (100.f/1024.f);
    }
}

// ---------------- launch: fork/join overlap of prep_w tail with GEMM head ---
extern "C" void kernel_launch(void* const* d_in, const int* in_sizes, int n_in,
                              void* d_out, int out_size) {
    const float* x      = (const float*)d_in[0];
    const float* factor = (const float*)d_in[1];
    const int*   label  = (const int*)  d_in[2];
    const float* w      = (const float*)d_in[3];
    float* out = (float*)d_out;

    cudaFuncSetAttribute(gemm_kernel, cudaFuncAttributeMaxDynamicSharedMemorySize, SMEM_BYTES);

    cudaStream_t s1;
    cudaStreamCreateWithFlags(&s1, cudaStreamNonBlocking);
    cudaEvent_t eFork, eJoin;
    cudaEventCreateWithFlags(&eFork, cudaEventDisableTiming);
    cudaEventCreateWithFlags(&eJoin, cudaEventDisableTiming);

    // fork: prep_w tail (cols NT1*64 .. OUTP) on s1, concurrent with head
    cudaEventRecord(eFork, 0);
    cudaStreamWaitEvent(s1, eFork, 0);
    {
        int ncols2 = (NT64 - NT1) * 64;               // 8064 (incl. pad cols)
        prep_w_kernel<<<(KCEN*ncols2)/256, 256, 0, s1>>>(w, NT1*64, ncols2);
    }

    // head on default stream
    prep_x_kernel<<<B_SZ, 128>>>(x, factor);
    prep_w_kernel<<<(KCEN*NT1*64)/256, 256>>>(w, 0, NT1*64);
    gemm_kernel<<<dim3(NT1, B_SZ/128), 256, SMEM_BYTES>>>(0);

    // join: remaining GEMM needs prep_w tail
    cudaEventRecord(eJoin, s1);
    cudaStreamWaitEvent(0, eJoin, 0);
    gemm_kernel<<<dim3(NT64 - NT1, B_SZ/128), 256, SMEM_BYTES>>>(NT1);

    epi_kernel<<<B_SZ, 256>>>(label);
    fin_kernel<<<1, 1024>>>(out);

    cudaStreamDestroy(s1);
    cudaEventDestroy(eFork);
    cudaEventDestroy(eJoin);
}

// round 11
// speedup vs baseline: 1.4262x; 1.0180x over previous
#include <cuda_runtime.h>
#include <cuda_fp16.h>
#include <cstdint>

#define B_SZ   1024
#define IN_SZ  128
#define OUT_SZ 10000
#define OUTP   10112            // 158 * 64, padded
#define KCEN   16
#define NT64   158              // n-tiles of 64 cols
#define NT1    32               // n-tiles (64-wide) in first GEMM chunk
#define SSC    64.0f

#define LDA 136                 // A pitch (halves): 128 + 8
#define LDB 72                  // B pitch (halves): 64 + 8
#define ATILE (128*LDA)
#define BTILE (128*LDB)
#define SMEM_HALVES (ATILE + 2*BTILE)
#define SMEM_BYTES  (SMEM_HALVES*2)      // 71680

// ---------------- device scratch ----------------
__device__ float4  g_xh4[(B_SZ*IN_SZ)/8];                      // 256 KB fp16
__device__ float4  g_wh4[((size_t)KCEN*IN_SZ*OUTP)/8];         // 41.4 MB fp16 (normalized)
__device__ __half2 g_cosh[((size_t)B_SZ*OUTP)/2 + 256];        // 20.7 MB fp16 cos (+pad)
__device__ float   g_cosfa[B_SZ], g_sinfa[B_SZ], g_costhr[B_SZ];
__device__ float   g_loss[B_SZ], g_corr[B_SZ];

// ---------------- prep_x ------------------------------------------------------
__global__ void prep_x_kernel(const float* __restrict__ x,
                              const float* __restrict__ factor) {
    int b = blockIdx.x, f = threadIdx.x;     // 128 threads
    float v = x[b*IN_SZ + f];
    float s = v*v;
    #pragma unroll
    for (int o = 16; o; o >>= 1) s += __shfl_xor_sync(0xffffffffu, s, o);
    __shared__ float ws[4];
    if ((f & 31) == 0) ws[f >> 5] = s;
    __syncthreads();
    float tot = ws[0] + ws[1] + ws[2] + ws[3];
    float rinv = 1.f / fmaxf(sqrtf(tot), 1e-12f);
    ((__half*)g_xh4)[b*IN_SZ + f] = __float2half(v * rinv);
    if (f == 0) {
        float fa = powf(1.5f, factor[b] * (1.f/12.f)) * 0.5f;
        float cfa = cosf(fa);
        g_cosfa[b] = cfa;
        g_sinfa[b] = sinf(fa);
        g_costhr[b] = -cfa;                  // cos(pi - fa)
    }
}

// ---------------- prep_w: 2-pass, column-range parameterized ------------------
__global__ void prep_w_kernel(const float* __restrict__ w, int o_base, int ncols) {
    int idx = blockIdx.x*blockDim.x + threadIdx.x;
    int k = idx / ncols, ol = idx - k*ncols;
    int o = o_base + ol;
    __half* wh = (__half*)g_wh4;
    size_t base = (size_t)k*IN_SZ*OUTP + o;
    if (o >= OUT_SZ) {
        for (int f = 0; f < IN_SZ; f++) wh[base + (size_t)f*OUTP] = __float2half(0.f);
        return;
    }
    const float* col = w + (size_t)k*IN_SZ*OUT_SZ + o;
    float s = 0.f;
    #pragma unroll 8
    for (int f = 0; f < IN_SZ; f++) { float v = col[(size_t)f*OUT_SZ]; s += v*v; }
    float rinv = 1.f / fmaxf(sqrtf(s), 1e-12f);
    #pragma unroll 8
    for (int f = 0; f < IN_SZ; f++)
        wh[base + (size_t)f*OUTP] = __float2half(col[(size_t)f*OUT_SZ] * rinv);
}

// ---------------- GEMM helpers -------------------------------------------------
__device__ __forceinline__ void cp_async16(uint32_t saddr, const void* gptr) {
    asm volatile("cp.async.cg.shared.global [%0], [%1], 16;\n" :: "r"(saddr), "l"(gptr));
}
#define CP_COMMIT() asm volatile("cp.async.commit_group;\n")
#define CP_WAIT1()  asm volatile("cp.async.wait_group 1;\n")

#define LDSM_X4(r0,r1,r2,r3,addr) \
    asm volatile("ldmatrix.sync.aligned.m8n8.x4.shared.b16 {%0,%1,%2,%3}, [%4];" \
        : "=r"(r0),"=r"(r1),"=r"(r2),"=r"(r3) : "r"(addr))
#define LDSM_X4_T(r0,r1,r2,r3,addr) \
    asm volatile("ldmatrix.sync.aligned.m8n8.x4.trans.shared.b16 {%0,%1,%2,%3}, [%4];" \
        : "=r"(r0),"=r"(r1),"=r"(r2),"=r"(r3) : "r"(addr))
// fp16-accumulate MMA: D,C = 2 b32 regs (rows r / r+8, cols c,c+1 packed)
#define MMA16816H(c0,c1,a0,a1,a2,a3,b0,b1) \
    asm volatile("mma.sync.aligned.m16n8k16.row.col.f16.f16.f16.f16 " \
        "{%0,%1},{%2,%3,%4,%5},{%6,%7},{%0,%1};" \
        : "+r"(c0),"+r"(c1) \
        : "r"(a0),"r"(a1),"r"(a2),"r"(a3),"r"(b0),"r"(b1))

// B tile: 128 k-rows x 64 n-cols = 8 chunks of 16B per row
__device__ __forceinline__ void load_b_tile(__half* Bs, const __half* wh,
                                            int tid, int n0, int kc, int buf) {
    int chunk = tid & 7, r0 = tid >> 3;          // 32 rows per pass of 256 thr
    const __half* src = wh + (size_t)kc*IN_SZ*OUTP + n0;
    __half* dst = Bs + buf*BTILE;
    #pragma unroll
    for (int it = 0; it < 4; it++) {
        int row = it*32 + r0;
        cp_async16((uint32_t)__cvta_generic_to_shared(dst + row*LDB + chunk*8),
                   src + (size_t)row*OUTP + chunk*8);
    }
}

// ---------------- main GEMM: 128x64 tile, 2 CTA/SM, f16-accum MMA -------------
__global__ void __launch_bounds__(256, 2) gemm_kernel(int nt0) {
    extern __shared__ __half sm[];
    __half* As = sm;
    __half* Bs = sm + ATILE;
    const __half* xh = (const __half*)g_xh4;
    const __half* wh = (const __half*)g_wh4;

    int tid = threadIdx.x;
    int n0 = (nt0 + blockIdx.x) * 64;
    int m0 = blockIdx.y * 128;

    {   // A tile: 128x128 halves
        int chunk = tid & 15, r0 = tid >> 4;
        #pragma unroll
        for (int it = 0; it < 8; it++) {
            int row = it*16 + r0;
            cp_async16((uint32_t)__cvta_generic_to_shared(As + row*LDA + chunk*8),
                       xh + (size_t)(m0 + row)*IN_SZ + chunk*8);
        }
    }
    load_b_tile(Bs, wh, tid, n0, 0, 0);
    CP_COMMIT();

    int wid = tid >> 5, lane = tid & 31;
    int wm = wid & 3, wn = wid >> 2;             // 4 m-warps x 2 n-warps (32x32 each)

    uint32_t smem_u32v = (uint32_t)__cvta_generic_to_shared(sm);
    uint32_t aA = smem_u32v + ((wm*32 + (lane & 15))*LDA + (lane >> 4)*8)*2;
    uint32_t aB = smem_u32v + ATILE*2 + ((lane & 15)*LDB + wn*32 + (lane >> 4)*8)*2;

    // running max in fp16 pairs: [mt][nt][0]=rows r, [1]=rows r+8 (cols c,c+1)
    __half2 mx2[2][4][2];
    const __half2 NEGH = __floats2half2_rn(-65504.f, -65504.f);
    #pragma unroll
    for (int i = 0; i < 2; i++)
        #pragma unroll
        for (int j = 0; j < 4; j++) { mx2[i][j][0] = NEGH; mx2[i][j][1] = NEGH; }

    for (int kc = 0; kc < KCEN; kc++) {
        int buf = kc & 1;
        if (kc < KCEN-1) load_b_tile(Bs, wh, tid, n0, kc+1, buf ^ 1);
        CP_COMMIT();
        CP_WAIT1();
        __syncthreads();

        uint32_t bbase = aB + buf*BTILE*2;

        // fp16 accumulators (2 b32 regs per MMA tile)
        uint32_t acc[2][4][2];
        #pragma unroll
        for (int i = 0; i < 2; i++)
            #pragma unroll
            for (int j = 0; j < 4; j++) { acc[i][j][0] = 0u; acc[i][j][1] = 0u; }

        // register-double-buffered fragments
        uint32_t a[2][2][4], bq[2][4][2];
        #pragma unroll
        for (int mt = 0; mt < 2; mt++)
            LDSM_X4(a[0][mt][0], a[0][mt][1], a[0][mt][2], a[0][mt][3],
                    aA + mt*16*LDA*2);
        #pragma unroll
        for (int p = 0; p < 2; p++)
            LDSM_X4_T(bq[0][2*p][0], bq[0][2*p][1], bq[0][2*p+1][0], bq[0][2*p+1][1],
                      bbase + p*32);

        #pragma unroll
        for (int ks = 0; ks < 8; ks++) {
            int cur = ks & 1, nxt = cur ^ 1;
            if (ks < 7) {
                #pragma unroll
                for (int mt = 0; mt < 2; mt++)
                    LDSM_X4(a[nxt][mt][0], a[nxt][mt][1], a[nxt][mt][2], a[nxt][mt][3],
                            aA + mt*16*LDA*2 + (ks+1)*32);
                #pragma unroll
                for (int p = 0; p < 2; p++)
                    LDSM_X4_T(bq[nxt][2*p][0], bq[nxt][2*p][1],
                              bq[nxt][2*p+1][0], bq[nxt][2*p+1][1],
                              bbase + (ks+1)*16*LDB*2 + p*32);
            }
            #pragma unroll
            for (int mt = 0; mt < 2; mt++)
                #pragma unroll
                for (int nt = 0; nt < 4; nt++)
                    MMA16816H(acc[mt][nt][0], acc[mt][nt][1],
                              a[cur][mt][0], a[cur][mt][1], a[cur][mt][2], a[cur][mt][3],
                              bq[cur][nt][0], bq[cur][nt][1]);
        }

        #pragma unroll
        for (int i = 0; i < 2; i++)
            #pragma unroll
            for (int j = 0; j < 4; j++) {
                mx2[i][j][0] = __hmax2(mx2[i][j][0], *(__half2*)&acc[i][j][0]);
                mx2[i][j][1] = __hmax2(mx2[i][j][1], *(__half2*)&acc[i][j][1]);
            }
        __syncthreads();
    }

    int rbase = m0 + wm*32 + (lane >> 2);
    int cbase = n0 + wn*32 + (lane & 3)*2;
    #pragma unroll
    for (int mt = 0; mt < 2; mt++)
        #pragma unroll
        for (int nt = 0; nt < 4; nt++) {
            int r = rbase + mt*16, c = cbase + nt*8;
            g_cosh[((size_t)r*OUTP + c) >> 1]     = mx2[mt][nt][0];
            g_cosh[((size_t)(r+8)*OUTP + c) >> 1] = mx2[mt][nt][1];
        }
}

// ---------------- epilogue: half2 input, batched, 2-phase ----------------------
__global__ void __launch_bounds__(256) epi_kernel(const int* __restrict__ label) {
    int r = blockIdx.x, t = threadIdx.x;     // 256 threads, 20 half2 each
    const __half2* row2 = g_cosh + (size_t)r*(OUTP/2);
    int lab = label[r];
    float cfa = g_cosfa[r], sfa = g_sinfa[r], cthr = g_costhr[r];

    __shared__ float s_mn[8], s_sum[8];
    __shared__ float s_lab;

    __half2 v2[20];
    #pragma unroll
    for (int j = 0; j < 20; j++)
        v2[j] = row2[j*256 + t];

    const float CLO = -1.0f + 1e-6f, CHI = 1.0f - 1e-6f;
    float mnon = -3.0e38f;
    #pragma unroll
    for (int j = 0; j < 20; j++) {
        int i = j*256 + t;
        if (i < OUT_SZ/2) {
            float c0 = fminf(fmaxf(__low2float(v2[j]),  CLO), CHI);
            float c1 = fminf(fmaxf(__high2float(v2[j]), CLO), CHI);
            int o0 = 2*i, o1 = 2*i + 1;
            if (o0 == lab) {
                s_lab = (c0 >= cthr)
                    ? (c0*cfa - sqrtf(fmaxf(1.f - c0*c0, 0.f))*sfa) * SSC
                    : c0 * SSC;
            } else mnon = fmaxf(mnon, c0 * SSC);
            if (o1 == lab) {
                s_lab = (c1 >= cthr)
                    ? (c1*cfa - sqrtf(fmaxf(1.f - c1*c1, 0.f))*sfa) * SSC
                    : c1 * SSC;
            } else mnon = fmaxf(mnon, c1 * SSC);
        }
    }
    #pragma unroll
    for (int o = 16; o; o >>= 1) mnon = fmaxf(mnon, __shfl_xor_sync(0xffffffffu, mnon, o));
    if ((t & 31) == 0) s_mn[t >> 5] = mnon;
    __syncthreads();
    float Mn = fmaxf(fmaxf(fmaxf(s_mn[0], s_mn[1]), fmaxf(s_mn[2], s_mn[3])),
                     fmaxf(fmaxf(s_mn[4], s_mn[5]), fmaxf(s_mn[6], s_mn[7])));
    float llab = s_lab;
    float M = fmaxf(Mn, llab);

    float s = 0.f;
    #pragma unroll
    for (int j = 0; j < 20; j++) {
        int i = j*256 + t;
        if (i < OUT_SZ/2) {
            float c0 = fminf(fmaxf(__low2float(v2[j]),  CLO), CHI);
            float c1 = fminf(fmaxf(__high2float(v2[j]), CLO), CHI);
            float l0 = (2*i     == lab) ? llab : c0 * SSC;
            float l1 = (2*i + 1 == lab) ? llab : c1 * SSC;
            s += __expf(l0 - M) + __expf(l1 - M);
        }
    }
    #pragma unroll
    for (int o = 16; o; o >>= 1) s += __shfl_xor_sync(0xffffffffu, s, o);
    if ((t & 31) == 0) s_sum[t >> 5] = s;
    __syncthreads();
    if (t == 0) {
        float S = s_sum[0]+s_sum[1]+s_sum[2]+s_sum[3]
                + s_sum[4]+s_sum[5]+s_sum[6]+s_sum[7];
        g_loss[r] = logf(S) + M - llab;
        g_corr[r] = (llab > Mn) ? 1.f : 0.f;
    }
}

// ---------------- final reduction ------------------------------------------
__global__ void fin_kernel(float* __restrict__ out) {
    int t = threadIdx.x;                     // 1024 threads
    __shared__ float sl[1024], sc[1024];
    sl[t] = g_loss[t]; sc[t] = g_corr[t];
    __syncthreads();
    for (int st = 512; st > 0; st >>= 1) {
        if (t < st) { sl[t] += sl[t+st]; sc[t] += sc[t+st]; }
        __syncthreads();
    }
    if (t == 0) {
        out[0] = sl[0] * (1.f/1024.f);
        out[1] = sc[0] * (100.f/1024.f);
    }
}

// ---------------- launch: fork/join overlap of prep_w tail with GEMM head ---
extern "C" void kernel_launch(void* const* d_in, const int* in_sizes, int n_in,
                              void* d_out, int out_size) {
    const float* x      = (const float*)d_in[0];
    const float* factor = (const float*)d_in[1];
    const int*   label  = (const int*)  d_in[2];
    const float* w      = (const float*)d_in[3];
    float* out = (float*)d_out;

    cudaFuncSetAttribute(gemm_kernel, cudaFuncAttributeMaxDynamicSharedMemorySize, SMEM_BYTES);

    cudaStream_t s1;
    cudaStreamCreateWithFlags(&s1, cudaStreamNonBlocking);
    cudaEvent_t eFork, eJoin;
    cudaEventCreateWithFlags(&eFork, cudaEventDisableTiming);
    cudaEventCreateWithFlags(&eJoin, cudaEventDisableTiming);

    // fork: prep_w tail (cols NT1*64 .. OUTP) on s1, concurrent with head
    cudaEventRecord(eFork, 0);
    cudaStreamWaitEvent(s1, eFork, 0);
    {
        int ncols2 = (NT64 - NT1) * 64;               // 8064 (incl. pad cols)
        prep_w_kernel<<<(KCEN*ncols2)/256, 256, 0, s1>>>(w, NT1*64, ncols2);
    }

    // head on default stream
    prep_x_kernel<<<B_SZ, 128>>>(x, factor);
    prep_w_kernel<<<(KCEN*NT1*64)/256, 256>>>(w, 0, NT1*64);
    gemm_kernel<<<dim3(NT1, B_SZ/128), 256, SMEM_BYTES>>>(0);

    // join: remaining GEMM needs prep_w tail
    cudaEventRecord(eJoin, s1);
    cudaStreamWaitEvent(0, eJoin, 0);
    gemm_kernel<<<dim3(NT64 - NT1, B_SZ/128), 256, SMEM_BYTES>>>(NT1);

    epi_kernel<<<B_SZ, 256>>>(label);
    fin_kernel<<<1, 1024>>>(out);

    cudaStreamDestroy(s1);
    cudaEventDestroy(eFork);
    cudaEventDestroy(eJoin);
}